// round 12
// baseline (speedup 1.0000x reference)
#include <cuda_runtime.h>
#include <cuda_fp16.h>
#include <cstdint>

// out[b,l,d] = sum_{i,j} x0[b,i,d] * x1[b,j,d] * filters[i*64+j, l]
// B=2048, F1=F2=64, D=16, L=16
//
// mma.sync m16n8k16 fp16, 2-term split (W = bh + bl; dropped x1_lo*W term
// ~2^-12 rel -> rel_err ~2e-4 < 1e-3), fp32 accum.
// Task = (batch-pair, l-half): warp owns 2 batches x 8 l-columns. Every B
// fragment feeds both batches (2x MMA per byte) and only its own l-half is
// loaded -> per-SM L1 B-traffic stays low at 14 warps/SM. ~110 regs, no cap hit.
// 4 independent MMA chains per warp ([mt][ks-half]), barrier-free, no smem.
// Grid 147 x 448 (14 warps) = 2058 warps >= 2048 tasks.

#define NW 14
#define NTHR (NW * 32)

__device__ __align__(16) unsigned char g_wbuf[262144];   // 8 ib x 32KB fragment-packed W

// ---------------- helpers ----------------
__device__ __forceinline__ uint32_t pkhf(float v0, float v1) {   // low half = v0
    __half2 t = __floats2half2_rn(v0, v1);
    return *(uint32_t*)&t;
}
__device__ __forceinline__ void mma_f16(float* c, const uint32_t* a,
                                        uint32_t b0, uint32_t b1) {
    asm("mma.sync.aligned.m16n8k16.row.col.f32.f16.f16.f32 "
        "{%0,%1,%2,%3}, {%4,%5,%6,%7}, {%8,%9}, {%0,%1,%2,%3};"
        : "+f"(c[0]), "+f"(c[1]), "+f"(c[2]), "+f"(c[3])
        : "r"(a[0]), "r"(a[1]), "r"(a[2]), "r"(a[3]), "r"(b0), "r"(b1));
}

// ---------------- prep: W -> fp16 hi/lo, mma-fragment packed ----------------
__global__ void prep_kernel(const float* __restrict__ filt) {
    int idx = blockIdx.x * 256 + threadIdx.x;        // 16384 threads
    int lane = idx & 31;
    int ks   = (idx >> 5) & 3;
    int nt   = (idx >> 7) & 15;
    int ib   = idx >> 11;                            // 0..7
    int np   = lane >> 2;                            // col within ntile
    int cg   = nt * 8 + np;                          // global col 0..127
    int il   = cg >> 4, l = cg & 15;
    int jb   = ks * 16 + (lane & 3) * 2;
    const float* base = filt + (ib * 8 + il) * 64 * 16 + l;
    float f0 = base[jb * 16],       f1 = base[(jb + 1) * 16];
    float f2 = base[(jb + 8) * 16], f3 = base[(jb + 9) * 16];
    __half h0 = __float2half_rn(f0), h1 = __float2half_rn(f1);
    __half h2 = __float2half_rn(f2), h3 = __float2half_rn(f3);
    float l0 = f0 - __half2float(h0), l1 = f1 - __half2float(h1);
    float l2 = f2 - __half2float(h2), l3 = f3 - __half2float(h3);
    uint4 o;
    o.x = pkhf(__half2float(h0), __half2float(h1));  // b_hi (k lo pair, k hi pair)
    o.y = pkhf(__half2float(h2), __half2float(h3));
    o.z = pkhf(l0, l1);                              // b_lo
    o.w = pkhf(l2, l3);
    *(uint4*)(g_wbuf + ib * 32768 + ((nt * 4 + ks) * 32 + lane) * 16) = o;
}

// ---------------- main ----------------
__global__ void __launch_bounds__(NTHR, 1)
efm_mma_kernel(const float* __restrict__ x0g, const float* __restrict__ x1g,
               float* __restrict__ outg)
{
    const int lane = threadIdx.x & 31;
    const int gw   = blockIdx.x * NW + (threadIdx.x >> 5);   // global warp task
    if (gw >= 2048) return;
    const int pair = gw >> 1;                        // batch-pair 0..1023
    const int lhi  = gw & 1;                         // l-half 0/1
    const int b0   = pair * 2;
    const int r0 = lane >> 2, k0 = (lane & 3) * 2;

    // ---- A fragments from x1 (fp16, single term): 2 batches x 4 ks x 4 regs ----
    uint32_t ah[2][4][4];
    #pragma unroll
    for (int mt = 0; mt < 2; mt++) {
        const float* xb = x1g + (b0 + mt) * 1024;
        #pragma unroll
        for (int ks = 0; ks < 4; ks++)
            #pragma unroll
            for (int p4 = 0; p4 < 4; p4++) {
                int row = r0 + (p4 & 1) * 8;
                int kb  = ks * 16 + k0 + (p4 >> 1) * 8;
                float v0 = __ldg(xb + kb * 16 + row);
                float v1 = __ldg(xb + (kb + 1) * 16 + row);
                ah[mt][ks][p4] = pkhf(v0, v1);
            }
    }

    float acc[2][2][2];                              // [mt][row][e]
    #pragma unroll
    for (int a = 0; a < 2; a++)
        #pragma unroll
        for (int bq = 0; bq < 2; bq++)
            #pragma unroll
            for (int c = 0; c < 2; c++) acc[a][bq][c] = 0.f;

    const float* x0a = x0g + b0 * 1024 + r0;
    const float* x0b = x0g + (b0 + 1) * 1024 + r0;

    #pragma unroll 1
    for (int ib = 0; ib < 8; ib++) {
        const uint4* Bi = (const uint4*)(g_wbuf + ib * 32768) + lhi * 4 * 32 + lane;

        #pragma unroll
        for (int p = 0; p < 8; p++) {
            // B fragments for nt = 2p + lhi: {bh0,bh1,bl0,bl1} per ks
            uint4 bv[4];
            #pragma unroll
            for (int ks = 0; ks < 4; ks++)
                bv[ks] = __ldg(Bi + ((2 * p) * 4 + ks) * 32);
            const int i = ib * 8 + p;
            float x0v[2][2];
            x0v[0][0] = __ldg(x0a + i * 16);
            x0v[0][1] = __ldg(x0a + i * 16 + 8);
            x0v[1][0] = __ldg(x0b + i * 16);
            x0v[1][1] = __ldg(x0b + i * 16 + 8);

            // 4 independent chains: [mt][ks-half], depth 4 each
            float c[2][2][4] = {{{0.f,0.f,0.f,0.f},{0.f,0.f,0.f,0.f}},
                                {{0.f,0.f,0.f,0.f},{0.f,0.f,0.f,0.f}}};
            #pragma unroll
            for (int ks = 0; ks < 4; ks++) {
                const int kh = ks >> 1;
                mma_f16(c[0][kh], ah[0][ks], bv[ks].x, bv[ks].y);   // hi term
                mma_f16(c[1][kh], ah[1][ks], bv[ks].x, bv[ks].y);
                mma_f16(c[0][kh], ah[0][ks], bv[ks].z, bv[ks].w);   // lo term
                mma_f16(c[1][kh], ah[1][ks], bv[ks].z, bv[ks].w);
            }
            #pragma unroll
            for (int mt = 0; mt < 2; mt++)
                #pragma unroll
                for (int r = 0; r < 2; r++)
                    #pragma unroll
                    for (int e = 0; e < 2; e++)
                        acc[mt][r][e] += x0v[mt][r] *
                            (c[mt][0][r * 2 + e] + c[mt][1][r * 2 + e]);
        }
    }

    // ---- output: per lane 2 mt x 2 rows x 2 l (this warp's l-half) ----
    #pragma unroll
    for (int mt = 0; mt < 2; mt++)
        #pragma unroll
        for (int r = 0; r < 2; r++)
            #pragma unroll
            for (int e = 0; e < 2; e++) {
                int l = lhi * 8 + (lane & 3) * 2 + e;
                int d = r0 + r * 8;
                outg[(b0 + mt) * 256 + l * 16 + d] = acc[mt][r][e];
            }
}

extern "C" void kernel_launch(void* const* d_in, const int* in_sizes, int n_in,
                              void* d_out, int out_size)
{
    const float* x0   = (const float*)d_in[0];   // [2048, 64, 16]
    const float* x1   = (const float*)d_in[1];   // [2048, 64, 16]
    const float* filt = (const float*)d_in[2];   // [1, 4096, 16]
    float* out        = (float*)d_out;           // [2048, 16, 16]

    prep_kernel<<<64, 256>>>(filt);
    efm_mma_kernel<<<147, NTHR>>>(x0, x1, out);  // 147*14 = 2058 >= 2048 tasks
}